// round 11
// baseline (speedup 1.0000x reference)
#include <cuda_runtime.h>
#include <math.h>

#define NB 64
#define NT 512
#define NV 512
#define NH 256
#define NO 512
#define MR (NB * NT)   // 32768 rows

// Scratch (allocation-free rule: __device__ globals)
__device__ float g_xproj[(size_t)MR * NH];   // x@W_ih^T + b_ih + b_hh
__device__ float g_hidden[(size_t)MR * NH];  // min(relu(h),1)

typedef unsigned long long ull;

__device__ __forceinline__ ull fma2(ull a, ull b, ull c) {
    ull d;
    asm("fma.rn.f32x2 %0, %1, %2, %3;" : "=l"(d) : "l"(a), "l"(b), "l"(c));
    return d;
}
__device__ __forceinline__ ull pack2(float lo, float hi) {
    ull r;
    unsigned int l = __float_as_uint(lo), h = __float_as_uint(hi);
    asm("mov.b64 %0, {%1, %2};" : "=l"(r) : "r"(l), "r"(h));
    return r;
}
__device__ __forceinline__ float2 unpack2(ull v) {
    unsigned int l, h;
    asm("mov.b64 {%0, %1}, %2;" : "=r"(l), "=r"(h) : "l"(v));
    return make_float2(__uint_as_float(l), __uint_as_float(h));
}

// ---------------------------------------------------------------------------
// GEMM: C[m,n] = epi( sum_k A[m,k]*Bw[n,k] + bias )   (both operands K-major)
// BM=BN=128, BK=16, 256 threads, 8x8 micro-tile via f32x2 packed FMA.
// B stored DUPLICATED in smem (each value twice) so the inner loop loads
// broadcast f32x2 pairs directly -> no pack2/MOVs per k (54 -> 40 issues/k).
// Double-buffered dynamic smem (50.7 KB), one __syncthreads per k-tile.
// EPI==0: + bias1[n] + bias2[n]      EPI==1: sigmoid(x + bias1[n])
// ---------------------------------------------------------------------------
#define AS_ROW 132
#define BS_ROW 264
#define GEMM_SMEM ((2 * 16 * AS_ROW + 2 * 16 * BS_ROW) * (int)sizeof(float))

template<int EPI>
__global__ void __launch_bounds__(256, 2)
gemm_nt(const float* __restrict__ A, const float* __restrict__ Bw,
        const float* __restrict__ bias1, const float* __restrict__ bias2,
        float* __restrict__ C, int M, int N, int K)
{
    extern __shared__ __align__(16) float sm[];
    float* Asf = sm;                        // [2][16][AS_ROW]
    float* Bsf = sm + 2 * 16 * AS_ROW;      // [2][16][BS_ROW] (duplicated vals)
    const int tid = threadIdx.x;
    const int m0 = blockIdx.y << 7;
    const int n0 = blockIdx.x << 7;
    const int ar = tid >> 2;          // 0..63
    const int ac = (tid & 3) << 2;    // 0,4,8,12
    const float* Ag = A  + (size_t)(m0 + ar) * K + ac;
    const float* Bg = Bw + (size_t)(n0 + ar) * K + ac;
    const int tm = tid >> 4;          // 0..15 (row group of 8)
    const int tn = tid & 15;          // 0..15 (col group: tn*4 and tn*4+64)

    ull acc[4][8];
#pragma unroll
    for (int i = 0; i < 4; i++)
#pragma unroll
        for (int j = 0; j < 8; j++) acc[i][j] = 0ull;

    float4 a0 = *(const float4*)(Ag);
    float4 a1 = *(const float4*)(Ag + (size_t)64 * K);
    float4 b0 = *(const float4*)(Bg);
    float4 b1 = *(const float4*)(Bg + (size_t)64 * K);

    // store helpers (writer: thread covers rows ac..ac+3 of the k-tile)
    auto store_tile = [&](int bf) {
        float* Ab = Asf + bf * 16 * AS_ROW;
        Ab[(ac + 0) * AS_ROW + ar]      = a0.x; Ab[(ac + 1) * AS_ROW + ar]      = a0.y;
        Ab[(ac + 2) * AS_ROW + ar]      = a0.z; Ab[(ac + 3) * AS_ROW + ar]      = a0.w;
        Ab[(ac + 0) * AS_ROW + ar + 64] = a1.x; Ab[(ac + 1) * AS_ROW + ar + 64] = a1.y;
        Ab[(ac + 2) * AS_ROW + ar + 64] = a1.z; Ab[(ac + 3) * AS_ROW + ar + 64] = a1.w;
        float* Bb = Bsf + bf * 16 * BS_ROW;
        ull* r0 = (ull*)(Bb + (ac + 0) * BS_ROW);
        ull* r1 = (ull*)(Bb + (ac + 1) * BS_ROW);
        ull* r2 = (ull*)(Bb + (ac + 2) * BS_ROW);
        ull* r3 = (ull*)(Bb + (ac + 3) * BS_ROW);
        r0[ar] = pack2(b0.x, b0.x); r0[ar + 64] = pack2(b1.x, b1.x);
        r1[ar] = pack2(b0.y, b0.y); r1[ar + 64] = pack2(b1.y, b1.y);
        r2[ar] = pack2(b0.z, b0.z); r2[ar + 64] = pack2(b1.z, b1.z);
        r3[ar] = pack2(b0.w, b0.w); r3[ar + 64] = pack2(b1.w, b1.w);
    };

    int buf = 0;
    store_tile(0);
    __syncthreads();

    for (int k0 = 0; k0 < K; k0 += 16) {
        const bool more = (k0 + 16) < K;
        if (more) {
            Ag += 16; Bg += 16;
            a0 = *(const float4*)(Ag);
            a1 = *(const float4*)(Ag + (size_t)64 * K);
            b0 = *(const float4*)(Bg);
            b1 = *(const float4*)(Bg + (size_t)64 * K);
        }
#pragma unroll
        for (int k = 0; k < 16; k++) {
            const float* Ak = Asf + (buf * 16 + k) * AS_ROW;
            const float* Bk = Bsf + (buf * 16 + k) * BS_ROW;
            ulonglong2 aA  = *(const ulonglong2*)(Ak + tm * 8);
            ulonglong2 aB  = *(const ulonglong2*)(Ak + tm * 8 + 4);
            ulonglong2 b01 = *(const ulonglong2*)(Bk + 8 * tn);
            ulonglong2 b23 = *(const ulonglong2*)(Bk + 8 * tn + 4);
            ulonglong2 b45 = *(const ulonglong2*)(Bk + 8 * tn + 128);
            ulonglong2 b67 = *(const ulonglong2*)(Bk + 8 * tn + 132);
            ull a2[4] = { aA.x, aA.y, aB.x, aB.y };
            ull bb[8] = { b01.x, b01.y, b23.x, b23.y,
                          b45.x, b45.y, b67.x, b67.y };
#pragma unroll
            for (int j = 0; j < 8; j++)
#pragma unroll
                for (int i = 0; i < 4; i++)
                    acc[i][j] = fma2(a2[i], bb[j], acc[i][j]);
        }
        if (more) {
            buf ^= 1;
            store_tile(buf);
            __syncthreads();
        }
    }

    float bv[8];
#pragma unroll
    for (int j = 0; j < 4; j++) {
        bv[j]     = bias1[n0 + tn * 4 + j];
        bv[4 + j] = bias1[n0 + tn * 4 + 64 + j];
    }
    if (EPI == 0) {
#pragma unroll
        for (int j = 0; j < 4; j++) {
            bv[j]     += bias2[n0 + tn * 4 + j];
            bv[4 + j] += bias2[n0 + tn * 4 + 64 + j];
        }
    }
#pragma unroll
    for (int i2 = 0; i2 < 4; i2++) {
        float2 v[8];
#pragma unroll
        for (int j = 0; j < 8; j++) v[j] = unpack2(acc[i2][j]);
#pragma unroll
        for (int half = 0; half < 2; half++) {
            int m = m0 + tm * 8 + i2 * 2 + half;
            float r[8];
#pragma unroll
            for (int j = 0; j < 8; j++) {
                float x = (half ? v[j].y : v[j].x) + bv[j];
                if (EPI == 1) x = 1.0f / (1.0f + expf(-x));
                r[j] = x;
            }
            *(float4*)&C[(size_t)m * N + n0 + tn * 4]      = make_float4(r[0], r[1], r[2], r[3]);
            *(float4*)&C[(size_t)m * N + n0 + tn * 4 + 64] = make_float4(r[4], r[5], r[6], r[7]);
        }
    }
}

// ---------------------------------------------------------------------------
// Recurrence: ONE CTA (256 threads) per batch element. Thread t owns column t.
//   W_hh[col][  0:208) -> 104 ull registers (208 regs/thread)
//   W_hh[col][208:256) -> dynamic smem ws2[i][col] (48 KB, 24 ull/col)
// h: double-buffered smem float[2][256]; loads are warp-broadcast.
// Crossbar/step: weights ~384 cyc + h-broadcast 512 + FMA issue ~512.
// ---------------------------------------------------------------------------
#define WS_ULL 24   // 24 ull = 48 floats per column from smem (js 208..255)
#define WR_ULL 104  // 104 ull = 208 floats per column in registers

__global__ void __launch_bounds__(256, 1)
rnn_scan(const float* __restrict__ W_hh, const float* __restrict__ prev,
         float* __restrict__ hn_out)
{
    extern __shared__ __align__(16) char smem_raw[];
    ull*   ws2 = (ull*)smem_raw;                       // [WS_ULL][256] -> 48 KB
    float* hb  = (float*)(smem_raw + WS_ULL * 256 * sizeof(ull)); // [2][256]

    const int col = threadIdx.x;      // 0..255, one output column per thread
    const int b   = blockIdx.x;

    // Register weights: W_hh[col][0:208) as 104 f32x2
    ull w2[WR_ULL];
    {
        const ull* wrow = (const ull*)(W_hh + (size_t)col * NH);
#pragma unroll
        for (int q = 0; q < WR_ULL; q++) w2[q] = wrow[q];
        // Smem weights: W_hh[col][208:256) -> ws2[i][col]
#pragma unroll
        for (int i = 0; i < WS_ULL; i++) ws2[i * 256 + col] = wrow[WR_ULL + i];
    }

    // h0
    hb[col] = prev[b * NH + col];
    __syncthreads();

    const float* xrow  = g_xproj  + ((size_t)b * NT) * NH + col;
    float*       hidro = g_hidden + ((size_t)b * NT) * NH + col;
    float xp0 = xrow[0];
    float xp1 = xrow[NH];

    int p = 0;
    for (int t = 0; t < NT; t++) {
        float xp = xp0;
        xp0 = xp1;
        if (t + 2 < NT) xp1 = xrow[(size_t)(t + 2) * NH];   // depth-2 prefetch

        const ulonglong2* hp = (const ulonglong2*)(hb + p * 256);
        ull a0 = 0ull, a1 = 0ull, a2 = 0ull, a3 = 0ull;     // 4 chains
        // register-weight part: js 0..207 (26 x 32B h chunks, broadcast)
#pragma unroll
        for (int q = 0; q < 26; q++) {
            ulonglong2 h0 = hp[2 * q];
            ulonglong2 h1 = hp[2 * q + 1];
            a0 = fma2(w2[4 * q],     h0.x, a0);
            a1 = fma2(w2[4 * q + 1], h0.y, a1);
            a2 = fma2(w2[4 * q + 2], h1.x, a2);
            a3 = fma2(w2[4 * q + 3], h1.y, a3);
        }
        // smem-weight part: js 208..255 (12 x 16B h chunks)
#pragma unroll
        for (int q = 0; q < 12; q++) {
            ulonglong2 hv = hp[52 + q];
            ull wA = ws2[(2 * q)     * 256 + col];
            ull wB = ws2[(2 * q + 1) * 256 + col];
            a0 = fma2(wA, hv.x, a0);
            a1 = fma2(wB, hv.y, a1);
        }
        float2 f0 = unpack2(a0), f1 = unpack2(a1), f2 = unpack2(a2), f3 = unpack2(a3);
        float tot = ((f0.x + f0.y) + (f1.x + f1.y)) + ((f2.x + f2.y) + (f3.x + f3.y));

        float h = fmaxf(tot + xp, 0.0f);
        hb[(p ^ 1) * 256 + col] = h;                 // next step's h
        // streaming store: g_hidden is consumed by a later kernel
        asm volatile("st.global.cs.f32 [%0], %1;"
                     :: "l"(hidro + (size_t)t * NH), "f"(fminf(h, 1.0f)) : "memory");
        if (t == NT - 1) hn_out[b * NH + col] = h;
        __syncthreads();
        p ^= 1;
    }
}

// ---------------------------------------------------------------------------
extern "C" void kernel_launch(void* const* d_in, const int* in_sizes, int n_in,
                              void* d_out, int out_size)
{
    const float* sentence = (const float*)d_in[0];
    const float* prev     = (const float*)d_in[1];
    const float* W_ih     = (const float*)d_in[2];
    const float* b_ih     = (const float*)d_in[3];
    const float* W_hh     = (const float*)d_in[4];
    const float* b_hh     = (const float*)d_in[5];
    const float* W_out    = (const float*)d_in[6];
    const float* b_out    = (const float*)d_in[7];
    float* out = (float*)d_out;

    float* xproj = nullptr;
    float* hidden = nullptr;
    cudaGetSymbolAddress((void**)&xproj, g_xproj);
    cudaGetSymbolAddress((void**)&hidden, g_hidden);

    const int scan_smem = WS_ULL * 256 * (int)sizeof(ull) + 2 * 256 * (int)sizeof(float);
    // idempotent, non-enqueuing attribute sets: capture-safe
    cudaFuncSetAttribute(rnn_scan, cudaFuncAttributeMaxDynamicSharedMemorySize,
                         scan_smem);
    cudaFuncSetAttribute(gemm_nt<0>, cudaFuncAttributeMaxDynamicSharedMemorySize,
                         GEMM_SMEM);
    cudaFuncSetAttribute(gemm_nt<1>, cudaFuncAttributeMaxDynamicSharedMemorySize,
                         GEMM_SMEM);

    // Phase 1: x_proj = sentence @ W_ih^T + (b_ih + b_hh)
    gemm_nt<0><<<dim3(NH / 128, MR / 128), 256, GEMM_SMEM>>>(
        sentence, W_ih, b_ih, b_hh, xproj, MR, NH, NV);
    // Phase 2: sequential scan; writes g_hidden and h_n (tail of d_out)
    rnn_scan<<<NB, 256, scan_smem>>>(W_hh, prev, out + (size_t)MR * NO);
    // Phase 3: tags = sigmoid(hidden @ W_out^T + b_out)
    gemm_nt<1><<<dim3(NO / 128, MR / 128), 256, GEMM_SMEM>>>(
        hidden, W_out, b_out, nullptr, out, MR, NO, NH);
}

// round 13
// speedup vs baseline: 1.2570x; 1.2570x over previous
#include <cuda_runtime.h>
#include <math.h>

#define NB 64
#define NT 512
#define NV 512
#define NH 256
#define NO 512
#define MR (NB * NT)   // 32768 rows

// Scratch (allocation-free rule: __device__ globals)
__device__ float g_xproj[(size_t)MR * NH];   // x@W_ih^T + b_ih + b_hh
__device__ float g_hidden[(size_t)MR * NH];  // min(relu(h),1)

typedef unsigned long long ull;

__device__ __forceinline__ ull fma2(ull a, ull b, ull c) {
    ull d;
    asm("fma.rn.f32x2 %0, %1, %2, %3;" : "=l"(d) : "l"(a), "l"(b), "l"(c));
    return d;
}
__device__ __forceinline__ ull pack2(float lo, float hi) {
    ull r;
    unsigned int l = __float_as_uint(lo), h = __float_as_uint(hi);
    asm("mov.b64 %0, {%1, %2};" : "=l"(r) : "r"(l), "r"(h));
    return r;
}
__device__ __forceinline__ float2 unpack2(ull v) {
    unsigned int l, h;
    asm("mov.b64 {%0, %1}, %2;" : "=r"(l), "=r"(h) : "l"(v));
    return make_float2(__uint_as_float(l), __uint_as_float(h));
}

// ---------------------------------------------------------------------------
// GEMM: C[m,n] = epi( sum_k A[m,k]*Bw[n,k] + bias )   (both operands K-major)
// BM=BN=128, BK=16, 256 threads, 8x8 micro-tile via f32x2 packed FMA.
// B duplicated in smem with a PLANE layout so every inner-loop B read is a
// 16B-chunk array at 16B stride (conflict-free, like A):
//   per k-row (130 ull): plane p in {0..3}, 16 chunks of 2 ull:
//     ull idx = p*32 + t*2 + half  holds dup(b[n]) where
//     n = (p>=2)*64 + 4*t + 2*(p&1) + half
// Reads: b01=plane0[tn], b23=plane1[tn], b45=plane2[tn], b67=plane3[tn].
// Per-k warp issues: 2 A-LDS + 4 B-LDS + 32 fma2 (no packs/MOVs).
// Double-buffered dynamic smem, one __syncthreads per k-tile.
// EPI==0: + bias1[n] + bias2[n]      EPI==1: sigmoid(x + bias1[n])
// ---------------------------------------------------------------------------
#define AS_ROW 132                 // floats per A k-row
#define BS_UROW 130                // ulls per B k-row (16B-aligned stride)
#define GEMM_SMEM (2 * 16 * (AS_ROW * (int)sizeof(float) + BS_UROW * (int)sizeof(ull)))

template<int EPI>
__global__ void __launch_bounds__(256, 2)
gemm_nt(const float* __restrict__ A, const float* __restrict__ Bw,
        const float* __restrict__ bias1, const float* __restrict__ bias2,
        float* __restrict__ C, int M, int N, int K)
{
    extern __shared__ __align__(16) char smraw[];
    ull*   Bsu = (ull*)smraw;                            // [2][16][BS_UROW]
    float* Asf = (float*)(smraw + 2 * 16 * BS_UROW * sizeof(ull)); // [2][16][AS_ROW]
    const int tid = threadIdx.x;
    const int m0 = blockIdx.y << 7;
    const int n0 = blockIdx.x << 7;
    const int ar = tid >> 2;          // 0..63
    const int ac = (tid & 3) << 2;    // 0,4,8,12
    const float* Ag = A  + (size_t)(m0 + ar) * K + ac;
    const float* Bg = Bw + (size_t)(n0 + ar) * K + ac;
    const int tm = tid >> 4;          // 0..15 (row group of 8)
    const int tn = tid & 15;          // 0..15 (col group: tn*4 and tn*4+64)

    // B dup write offsets within a k-row for n=ar (lo) and n=ar+64 (hi)
    const int blo = ((ar & 2) >> 1) * 32 + (ar >> 2) * 2 + (ar & 1);
    const int bhi = blo + 64;         // planes 2,3

    ull acc[4][8];
#pragma unroll
    for (int i = 0; i < 4; i++)
#pragma unroll
        for (int j = 0; j < 8; j++) acc[i][j] = 0ull;

    float4 a0 = *(const float4*)(Ag);
    float4 a1 = *(const float4*)(Ag + (size_t)64 * K);
    float4 b0 = *(const float4*)(Bg);
    float4 b1 = *(const float4*)(Bg + (size_t)64 * K);

    auto store_tile = [&](int bf) {
        float* Ab = Asf + bf * 16 * AS_ROW;
        Ab[(ac + 0) * AS_ROW + ar]      = a0.x; Ab[(ac + 1) * AS_ROW + ar]      = a0.y;
        Ab[(ac + 2) * AS_ROW + ar]      = a0.z; Ab[(ac + 3) * AS_ROW + ar]      = a0.w;
        Ab[(ac + 0) * AS_ROW + ar + 64] = a1.x; Ab[(ac + 1) * AS_ROW + ar + 64] = a1.y;
        Ab[(ac + 2) * AS_ROW + ar + 64] = a1.z; Ab[(ac + 3) * AS_ROW + ar + 64] = a1.w;
        ull* Bb = Bsu + (bf * 16 + ac) * BS_UROW;
        Bb[blo]               = pack2(b0.x, b0.x); Bb[bhi]               = pack2(b1.x, b1.x);
        Bb[BS_UROW + blo]     = pack2(b0.y, b0.y); Bb[BS_UROW + bhi]     = pack2(b1.y, b1.y);
        Bb[2 * BS_UROW + blo] = pack2(b0.z, b0.z); Bb[2 * BS_UROW + bhi] = pack2(b1.z, b1.z);
        Bb[3 * BS_UROW + blo] = pack2(b0.w, b0.w); Bb[3 * BS_UROW + bhi] = pack2(b1.w, b1.w);
    };

    int buf = 0;
    store_tile(0);
    __syncthreads();

    for (int k0 = 0; k0 < K; k0 += 16) {
        const bool more = (k0 + 16) < K;
        if (more) {
            Ag += 16; Bg += 16;
            a0 = *(const float4*)(Ag);
            a1 = *(const float4*)(Ag + (size_t)64 * K);
            b0 = *(const float4*)(Bg);
            b1 = *(const float4*)(Bg + (size_t)64 * K);
        }
#pragma unroll
        for (int k = 0; k < 16; k++) {
            const float* Ak = Asf + (buf * 16 + k) * AS_ROW;
            const ull*   Bk = Bsu + (buf * 16 + k) * BS_UROW;
            ulonglong2 aA  = *(const ulonglong2*)(Ak + tm * 8);
            ulonglong2 aB  = *(const ulonglong2*)(Ak + tm * 8 + 4);
            ulonglong2 b01 = *(const ulonglong2*)(Bk + 2 * tn);        // plane 0
            ulonglong2 b23 = *(const ulonglong2*)(Bk + 32 + 2 * tn);   // plane 1
            ulonglong2 b45 = *(const ulonglong2*)(Bk + 64 + 2 * tn);   // plane 2
            ulonglong2 b67 = *(const ulonglong2*)(Bk + 96 + 2 * tn);   // plane 3
            ull a2[4] = { aA.x, aA.y, aB.x, aB.y };
            ull bb[8] = { b01.x, b01.y, b23.x, b23.y,
                          b45.x, b45.y, b67.x, b67.y };
#pragma unroll
            for (int j = 0; j < 8; j++)
#pragma unroll
                for (int i = 0; i < 4; i++)
                    acc[i][j] = fma2(a2[i], bb[j], acc[i][j]);
        }
        if (more) {
            buf ^= 1;
            store_tile(buf);
            __syncthreads();
        }
    }

    float bv[8];
#pragma unroll
    for (int j = 0; j < 4; j++) {
        bv[j]     = bias1[n0 + tn * 4 + j];
        bv[4 + j] = bias1[n0 + tn * 4 + 64 + j];
    }
    if (EPI == 0) {
#pragma unroll
        for (int j = 0; j < 4; j++) {
            bv[j]     += bias2[n0 + tn * 4 + j];
            bv[4 + j] += bias2[n0 + tn * 4 + 64 + j];
        }
    }
#pragma unroll
    for (int i2 = 0; i2 < 4; i2++) {
        float2 v[8];
#pragma unroll
        for (int j = 0; j < 8; j++) v[j] = unpack2(acc[i2][j]);
#pragma unroll
        for (int half = 0; half < 2; half++) {
            int m = m0 + tm * 8 + i2 * 2 + half;
            float r[8];
#pragma unroll
            for (int j = 0; j < 8; j++) {
                float x = (half ? v[j].y : v[j].x) + bv[j];
                if (EPI == 1) x = 1.0f / (1.0f + expf(-x));
                r[j] = x;
            }
            *(float4*)&C[(size_t)m * N + n0 + tn * 4]      = make_float4(r[0], r[1], r[2], r[3]);
            *(float4*)&C[(size_t)m * N + n0 + tn * 4 + 64] = make_float4(r[4], r[5], r[6], r[7]);
        }
    }
}

// ---------------------------------------------------------------------------
// Recurrence (unchanged from R11 — measured ~360us): ONE CTA per batch.
//   W_hh[col][  0:208) -> 104 ull registers
//   W_hh[col][208:256) -> dynamic smem ws2[i][col] (48 KB)
// h: double-buffered smem float[2][256]; loads are warp-broadcast.
// ---------------------------------------------------------------------------
#define WS_ULL 24   // 24 ull = 48 floats per column from smem (js 208..255)
#define WR_ULL 104  // 104 ull = 208 floats per column in registers

__global__ void __launch_bounds__(256, 1)
rnn_scan(const float* __restrict__ W_hh, const float* __restrict__ prev,
         float* __restrict__ hn_out)
{
    extern __shared__ __align__(16) char smem_raw[];
    ull*   ws2 = (ull*)smem_raw;                       // [WS_ULL][256] -> 48 KB
    float* hb  = (float*)(smem_raw + WS_ULL * 256 * sizeof(ull)); // [2][256]

    const int col = threadIdx.x;      // 0..255, one output column per thread
    const int b   = blockIdx.x;

    ull w2[WR_ULL];
    {
        const ull* wrow = (const ull*)(W_hh + (size_t)col * NH);
#pragma unroll
        for (int q = 0; q < WR_ULL; q++) w2[q] = wrow[q];
#pragma unroll
        for (int i = 0; i < WS_ULL; i++) ws2[i * 256 + col] = wrow[WR_ULL + i];
    }

    hb[col] = prev[b * NH + col];
    __syncthreads();

    const float* xrow  = g_xproj  + ((size_t)b * NT) * NH + col;
    float*       hidro = g_hidden + ((size_t)b * NT) * NH + col;
    float xp0 = xrow[0];
    float xp1 = xrow[NH];

    int p = 0;
    for (int t = 0; t < NT; t++) {
        float xp = xp0;
        xp0 = xp1;
        if (t + 2 < NT) xp1 = xrow[(size_t)(t + 2) * NH];   // depth-2 prefetch

        const ulonglong2* hp = (const ulonglong2*)(hb + p * 256);
        ull a0 = 0ull, a1 = 0ull, a2 = 0ull, a3 = 0ull;     // 4 chains
#pragma unroll
        for (int q = 0; q < 26; q++) {
            ulonglong2 h0 = hp[2 * q];
            ulonglong2 h1 = hp[2 * q + 1];
            a0 = fma2(w2[4 * q],     h0.x, a0);
            a1 = fma2(w2[4 * q + 1], h0.y, a1);
            a2 = fma2(w2[4 * q + 2], h1.x, a2);
            a3 = fma2(w2[4 * q + 3], h1.y, a3);
        }
#pragma unroll
        for (int q = 0; q < 12; q++) {
            ulonglong2 hv = hp[52 + q];
            ull wA = ws2[(2 * q)     * 256 + col];
            ull wB = ws2[(2 * q + 1) * 256 + col];
            a0 = fma2(wA, hv.x, a0);
            a1 = fma2(wB, hv.y, a1);
        }
        float2 f0 = unpack2(a0), f1 = unpack2(a1), f2 = unpack2(a2), f3 = unpack2(a3);
        float tot = ((f0.x + f0.y) + (f1.x + f1.y)) + ((f2.x + f2.y) + (f3.x + f3.y));

        float h = fmaxf(tot + xp, 0.0f);
        hb[(p ^ 1) * 256 + col] = h;                 // next step's h
        asm volatile("st.global.cs.f32 [%0], %1;"
                     :: "l"(hidro + (size_t)t * NH), "f"(fminf(h, 1.0f)) : "memory");
        if (t == NT - 1) hn_out[b * NH + col] = h;
        __syncthreads();
        p ^= 1;
    }
}

// ---------------------------------------------------------------------------
extern "C" void kernel_launch(void* const* d_in, const int* in_sizes, int n_in,
                              void* d_out, int out_size)
{
    const float* sentence = (const float*)d_in[0];
    const float* prev     = (const float*)d_in[1];
    const float* W_ih     = (const float*)d_in[2];
    const float* b_ih     = (const float*)d_in[3];
    const float* W_hh     = (const float*)d_in[4];
    const float* b_hh     = (const float*)d_in[5];
    const float* W_out    = (const float*)d_in[6];
    const float* b_out    = (const float*)d_in[7];
    float* out = (float*)d_out;

    float* xproj = nullptr;
    float* hidden = nullptr;
    cudaGetSymbolAddress((void**)&xproj, g_xproj);
    cudaGetSymbolAddress((void**)&hidden, g_hidden);

    const int scan_smem = WS_ULL * 256 * (int)sizeof(ull) + 2 * 256 * (int)sizeof(float);
    // idempotent, non-enqueuing attribute sets: capture-safe
    cudaFuncSetAttribute(rnn_scan, cudaFuncAttributeMaxDynamicSharedMemorySize,
                         scan_smem);
    cudaFuncSetAttribute(gemm_nt<0>, cudaFuncAttributeMaxDynamicSharedMemorySize,
                         GEMM_SMEM);
    cudaFuncSetAttribute(gemm_nt<1>, cudaFuncAttributeMaxDynamicSharedMemorySize,
                         GEMM_SMEM);

    // Phase 1: x_proj = sentence @ W_ih^T + (b_ih + b_hh)
    gemm_nt<0><<<dim3(NH / 128, MR / 128), 256, GEMM_SMEM>>>(
        sentence, W_ih, b_ih, b_hh, xproj, MR, NH, NV);
    // Phase 2: sequential scan; writes g_hidden and h_n (tail of d_out)
    rnn_scan<<<NB, 256, scan_smem>>>(W_hh, prev, out + (size_t)MR * NO);
    // Phase 3: tags = sigmoid(hidden @ W_out^T + b_out)
    gemm_nt<1><<<dim3(NO / 128, MR / 128), 256, GEMM_SMEM>>>(
        hidden, W_out, b_out, nullptr, out, MR, NO, NH);
}

// round 14
// speedup vs baseline: 1.4407x; 1.1462x over previous
#include <cuda_runtime.h>
#include <math.h>

#define NB 64
#define NT 512
#define NV 512
#define NH 256
#define NO 512
#define MR (NB * NT)   // 32768 rows

// Scratch (allocation-free rule: __device__ globals)
__device__ float g_xproj[(size_t)MR * NH];   // x@W_ih^T + b_ih + b_hh
__device__ float g_hidden[(size_t)MR * NH];  // min(relu(h),1)

typedef unsigned long long ull;

__device__ __forceinline__ ull fma2(ull a, ull b, ull c) {
    ull d;
    asm("fma.rn.f32x2 %0, %1, %2, %3;" : "=l"(d) : "l"(a), "l"(b), "l"(c));
    return d;
}
__device__ __forceinline__ ull pack2(float lo, float hi) {
    ull r;
    unsigned int l = __float_as_uint(lo), h = __float_as_uint(hi);
    asm("mov.b64 %0, {%1, %2};" : "=l"(r) : "r"(l), "r"(h));
    return r;
}
__device__ __forceinline__ float2 unpack2(ull v) {
    unsigned int l, h;
    asm("mov.b64 {%0, %1}, %2;" : "=r"(l), "=r"(h) : "l"(v));
    return make_float2(__uint_as_float(l), __uint_as_float(h));
}

// ---------------------------------------------------------------------------
// GEMM (REVERTED to R4 — measured 173us): BM=BN=128, BK=16, 256 threads,
// 8x8 micro-tile via f32x2 packed FMA, static double-buffered smem,
// one __syncthreads per k-tile.
// EPI==0: + bias1[n] + bias2[n]      EPI==1: sigmoid(x + bias1[n])
// ---------------------------------------------------------------------------
template<int EPI>
__global__ void __launch_bounds__(256, 2)
gemm_nt(const float* __restrict__ A, const float* __restrict__ Bw,
        const float* __restrict__ bias1, const float* __restrict__ bias2,
        float* __restrict__ C, int M, int N, int K)
{
    __shared__ __align__(16) float As[2][16][132];
    __shared__ __align__(16) float Bs[2][16][132];
    const int tid = threadIdx.x;
    const int m0 = blockIdx.y << 7;
    const int n0 = blockIdx.x << 7;
    const int ar = tid >> 2;          // 0..63
    const int ac = (tid & 3) << 2;    // 0,4,8,12
    const float* Ag = A  + (size_t)(m0 + ar) * K + ac;
    const float* Bg = Bw + (size_t)(n0 + ar) * K + ac;
    const int tm = tid >> 4;          // 0..15 (row group of 8)
    const int tn = tid & 15;          // 0..15 (col group: tn*4 and tn*4+64)

    ull acc[4][8];
#pragma unroll
    for (int i = 0; i < 4; i++)
#pragma unroll
        for (int j = 0; j < 8; j++) acc[i][j] = 0ull;

    float4 a0 = *(const float4*)(Ag);
    float4 a1 = *(const float4*)(Ag + (size_t)64 * K);
    float4 b0 = *(const float4*)(Bg);
    float4 b1 = *(const float4*)(Bg + (size_t)64 * K);
    int buf = 0;
    {
        As[0][ac + 0][ar]      = a0.x; As[0][ac + 1][ar]      = a0.y;
        As[0][ac + 2][ar]      = a0.z; As[0][ac + 3][ar]      = a0.w;
        As[0][ac + 0][ar + 64] = a1.x; As[0][ac + 1][ar + 64] = a1.y;
        As[0][ac + 2][ar + 64] = a1.z; As[0][ac + 3][ar + 64] = a1.w;
        Bs[0][ac + 0][ar]      = b0.x; Bs[0][ac + 1][ar]      = b0.y;
        Bs[0][ac + 2][ar]      = b0.z; Bs[0][ac + 3][ar]      = b0.w;
        Bs[0][ac + 0][ar + 64] = b1.x; Bs[0][ac + 1][ar + 64] = b1.y;
        Bs[0][ac + 2][ar + 64] = b1.z; Bs[0][ac + 3][ar + 64] = b1.w;
    }
    __syncthreads();

    for (int k0 = 0; k0 < K; k0 += 16) {
        const bool more = (k0 + 16) < K;
        if (more) {
            Ag += 16; Bg += 16;
            a0 = *(const float4*)(Ag);
            a1 = *(const float4*)(Ag + (size_t)64 * K);
            b0 = *(const float4*)(Bg);
            b1 = *(const float4*)(Bg + (size_t)64 * K);
        }
#pragma unroll
        for (int k = 0; k < 16; k++) {
            ulonglong2 aA = *(const ulonglong2*)&As[buf][k][tm * 8];
            ulonglong2 aB = *(const ulonglong2*)&As[buf][k][tm * 8 + 4];
            float4 bA = *(const float4*)&Bs[buf][k][tn * 4];
            float4 bB = *(const float4*)&Bs[buf][k][tn * 4 + 64];
            ull a2[4] = { aA.x, aA.y, aB.x, aB.y };
            ull bb[8] = { pack2(bA.x, bA.x), pack2(bA.y, bA.y),
                          pack2(bA.z, bA.z), pack2(bA.w, bA.w),
                          pack2(bB.x, bB.x), pack2(bB.y, bB.y),
                          pack2(bB.z, bB.z), pack2(bB.w, bB.w) };
#pragma unroll
            for (int j = 0; j < 8; j++)
#pragma unroll
                for (int i = 0; i < 4; i++)
                    acc[i][j] = fma2(a2[i], bb[j], acc[i][j]);
        }
        if (more) {
            int nb = buf ^ 1;
            As[nb][ac + 0][ar]      = a0.x; As[nb][ac + 1][ar]      = a0.y;
            As[nb][ac + 2][ar]      = a0.z; As[nb][ac + 3][ar]      = a0.w;
            As[nb][ac + 0][ar + 64] = a1.x; As[nb][ac + 1][ar + 64] = a1.y;
            As[nb][ac + 2][ar + 64] = a1.z; As[nb][ac + 3][ar + 64] = a1.w;
            Bs[nb][ac + 0][ar]      = b0.x; Bs[nb][ac + 1][ar]      = b0.y;
            Bs[nb][ac + 2][ar]      = b0.z; Bs[nb][ac + 3][ar]      = b0.w;
            Bs[nb][ac + 0][ar + 64] = b1.x; Bs[nb][ac + 1][ar + 64] = b1.y;
            Bs[nb][ac + 2][ar + 64] = b1.z; Bs[nb][ac + 3][ar + 64] = b1.w;
            __syncthreads();
            buf = nb;
        }
    }

    float bv[8];
#pragma unroll
    for (int j = 0; j < 4; j++) {
        bv[j]     = bias1[n0 + tn * 4 + j];
        bv[4 + j] = bias1[n0 + tn * 4 + 64 + j];
    }
    if (EPI == 0) {
#pragma unroll
        for (int j = 0; j < 4; j++) {
            bv[j]     += bias2[n0 + tn * 4 + j];
            bv[4 + j] += bias2[n0 + tn * 4 + 64 + j];
        }
    }
#pragma unroll
    for (int i2 = 0; i2 < 4; i2++) {
        float2 v[8];
#pragma unroll
        for (int j = 0; j < 8; j++) v[j] = unpack2(acc[i2][j]);
#pragma unroll
        for (int half = 0; half < 2; half++) {
            int m = m0 + tm * 8 + i2 * 2 + half;
            float r[8];
#pragma unroll
            for (int j = 0; j < 8; j++) {
                float x = (half ? v[j].y : v[j].x) + bv[j];
                if (EPI == 1) x = 1.0f / (1.0f + expf(-x));
                r[j] = x;
            }
            *(float4*)&C[(size_t)m * N + n0 + tn * 4]      = make_float4(r[0], r[1], r[2], r[3]);
            *(float4*)&C[(size_t)m * N + n0 + tn * 4 + 64] = make_float4(r[4], r[5], r[6], r[7]);
        }
    }
}

// ---------------------------------------------------------------------------
// Recurrence v2: ONE CTA (256 threads) per batch. NEW mapping to halve LDS:
// thread (part=tid&1, colg=tid>>1) computes PARTIAL dots for cols
// {colg, colg+128} over j in [part*128, part*128+128). Partials combined
// with one shfl_xor(1) per col (both lanes get both totals); even lane
// outputs col colg, odd lane outputs col colg+128.
//   weights/thread: 128 ull = 104 in regs (52/col) + 24 in smem (12/col),
//     smem pair layout wsu2[i][tid] (16B lane stride -> conflict-free LDS.128)
//   h loads/thread: 32 LDS.128 (halved vs v1)
// LDS-instr/thread-step: 32 h + 6 w = 38 -> LSU 304 cyc < fma floor 512.
// ---------------------------------------------------------------------------
#define WRC 52   // ull weights in registers per col (js 0..103 of the half)
#define WSC 6    // ulonglong2 weights in smem per col (js 104..127 of the half)

__global__ void __launch_bounds__(256, 1)
rnn_scan(const float* __restrict__ W_hh, const float* __restrict__ prev,
         float* __restrict__ hn_out)
{
    extern __shared__ __align__(16) char smem_raw[];
    ulonglong2* wsu2 = (ulonglong2*)smem_raw;          // [2*WSC][256] -> 48 KB
    float* hb = (float*)(smem_raw + 2 * WSC * 256 * sizeof(ulonglong2)); // [2][256]

    const int tid  = threadIdx.x;
    const int part = tid & 1;         // j-half: [part*128, part*128+128)
    const int colg = tid >> 1;        // 0..127
    const int b    = blockIdx.x;
    const int col_out = colg + part * 128;   // the column this lane outputs

    // Weights: rows colg and colg+128, j-half `part` (64 ull each)
    ull w0[WRC], w1[WRC];
    {
        const ull* wr0 = (const ull*)(W_hh + (size_t)colg * NH + part * 128);
        const ull* wr1 = (const ull*)(W_hh + (size_t)(colg + 128) * NH + part * 128);
#pragma unroll
        for (int q = 0; q < WRC; q++) { w0[q] = wr0[q]; w1[q] = wr1[q]; }
#pragma unroll
        for (int i = 0; i < WSC; i++) {
            wsu2[i * 256 + tid]         = make_ulonglong2(wr0[WRC + 2 * i], wr0[WRC + 2 * i + 1]);
            wsu2[(WSC + i) * 256 + tid] = make_ulonglong2(wr1[WRC + 2 * i], wr1[WRC + 2 * i + 1]);
        }
    }

    // h0
    hb[tid] = prev[b * NH + tid];
    __syncthreads();

    const float* xrow  = g_xproj  + ((size_t)b * NT) * NH + col_out;
    float*       hidro = g_hidden + ((size_t)b * NT) * NH + col_out;
    float xp0 = xrow[0];
    float xp1 = xrow[NH];

    int p = 0;
    for (int t = 0; t < NT; t++) {
        float xp = xp0;
        xp0 = xp1;
        if (t + 2 < NT) xp1 = xrow[(size_t)(t + 2) * NH];   // depth-2 prefetch

        // this thread reads h[part*128 .. part*128+128) : 32 LDS.128
        const ulonglong2* hp = (const ulonglong2*)(hb + p * 256 + part * 128);
        ull c0a = 0ull, c0b = 0ull, c1a = 0ull, c1b = 0ull;
#pragma unroll
        for (int q = 0; q < 26; q++) {
            ulonglong2 hv = hp[q];
            c0a = fma2(w0[2 * q],     hv.x, c0a);
            c0b = fma2(w0[2 * q + 1], hv.y, c0b);
            c1a = fma2(w1[2 * q],     hv.x, c1a);
            c1b = fma2(w1[2 * q + 1], hv.y, c1b);
        }
#pragma unroll
        for (int q = 26; q < 32; q++) {
            ulonglong2 hv = hp[q];
            ulonglong2 u0 = wsu2[(q - 26) * 256 + tid];
            ulonglong2 u1 = wsu2[(WSC + q - 26) * 256 + tid];
            c0a = fma2(u0.x, hv.x, c0a);
            c0b = fma2(u0.y, hv.y, c0b);
            c1a = fma2(u1.x, hv.x, c1a);
            c1b = fma2(u1.y, hv.y, c1b);
        }
        float2 e0 = unpack2(c0a), e1 = unpack2(c0b);
        float2 e2 = unpack2(c1a), e3 = unpack2(c1b);
        float t0 = (e0.x + e0.y) + (e1.x + e1.y);   // partial for col colg
        float t1 = (e2.x + e2.y) + (e3.x + e3.y);   // partial for col colg+128
        float tot0 = t0 + __shfl_xor_sync(0xffffffffu, t0, 1);
        float tot1 = t1 + __shfl_xor_sync(0xffffffffu, t1, 1);

        float h = fmaxf((part ? tot1 : tot0) + xp, 0.0f);
        hb[(p ^ 1) * 256 + col_out] = h;             // next step's h
        // streaming store: g_hidden is consumed by a later kernel
        asm volatile("st.global.cs.f32 [%0], %1;"
                     :: "l"(hidro + (size_t)t * NH), "f"(fminf(h, 1.0f)) : "memory");
        if (t == NT - 1) hn_out[b * NH + col_out] = h;
        __syncthreads();
        p ^= 1;
    }
}

// ---------------------------------------------------------------------------
extern "C" void kernel_launch(void* const* d_in, const int* in_sizes, int n_in,
                              void* d_out, int out_size)
{
    const float* sentence = (const float*)d_in[0];
    const float* prev     = (const float*)d_in[1];
    const float* W_ih     = (const float*)d_in[2];
    const float* b_ih     = (const float*)d_in[3];
    const float* W_hh     = (const float*)d_in[4];
    const float* b_hh     = (const float*)d_in[5];
    const float* W_out    = (const float*)d_in[6];
    const float* b_out    = (const float*)d_in[7];
    float* out = (float*)d_out;

    float* xproj = nullptr;
    float* hidden = nullptr;
    cudaGetSymbolAddress((void**)&xproj, g_xproj);
    cudaGetSymbolAddress((void**)&hidden, g_hidden);

    const int scan_smem = 2 * WSC * 256 * (int)sizeof(ulonglong2)
                        + 2 * 256 * (int)sizeof(float);
    // idempotent, non-enqueuing attribute set: capture-safe
    cudaFuncSetAttribute(rnn_scan, cudaFuncAttributeMaxDynamicSharedMemorySize,
                         scan_smem);

    // Phase 1: x_proj = sentence @ W_ih^T + (b_ih + b_hh)
    gemm_nt<0><<<dim3(NH / 128, MR / 128), 256>>>(sentence, W_ih, b_ih, b_hh,
                                                  xproj, MR, NH, NV);
    // Phase 2: sequential scan; writes g_hidden and h_n (tail of d_out)
    rnn_scan<<<NB, 256, scan_smem>>>(W_hh, prev, out + (size_t)MR * NO);
    // Phase 3: tags = sigmoid(hidden @ W_out^T + b_out)
    gemm_nt<1><<<dim3(NO / 128, MR / 128), 256>>>(hidden, W_out, b_out, nullptr,
                                                  out, MR, NO, NH);
}